// round 15
// baseline (speedup 1.0000x reference)
#include <cuda_runtime.h>
#include <cuda_bf16.h>
#include <math.h>

#define Bb 2
#define Tt 1024
#define Cc 2048
#define Hh 16
#define Dd 128
#define BT (Bb*Tt)

typedef unsigned long long u64;
typedef unsigned int u32;

// ================= portable tensor-core helpers ===================================
__device__ __forceinline__ u32 smem_u32_of(const void* p) {
    u32 a; asm("{ .reg .u64 t; cvta.to.shared.u64 t, %1; cvt.u32.u64 %0, t; }"
               : "=r"(a) : "l"(p));
    return a;
}
__device__ __forceinline__ void ldsm_x4(u32& r0, u32& r1, u32& r2, u32& r3, u32 addr) {
    asm volatile("ldmatrix.sync.aligned.m8n8.x4.shared.b16 {%0,%1,%2,%3}, [%4];"
                 : "=r"(r0), "=r"(r1), "=r"(r2), "=r"(r3) : "r"(addr));
}
__device__ __forceinline__ void mma16816(float* c, const u32* a, const u32* b) {
    asm volatile(
        "mma.sync.aligned.m16n8k16.row.col.f32.bf16.bf16.f32 "
        "{%0,%1,%2,%3}, {%4,%5,%6,%7}, {%8,%9}, {%0,%1,%2,%3};"
        : "+f"(c[0]), "+f"(c[1]), "+f"(c[2]), "+f"(c[3])
        : "r"(a[0]), "r"(a[1]), "r"(a[2]), "r"(a[3]), "r"(b[0]), "r"(b[1]));
}
__device__ __forceinline__ u32 pack_bf2(__nv_bfloat16 x, __nv_bfloat16 y) {
    __nv_bfloat162 t; t.x = x; t.y = y;
    return *(u32*)&t;
}
__device__ __forceinline__ u32 split2(float x, float y, u32& lo) {
    __nv_bfloat16 hx = __float2bfloat16(x);
    __nv_bfloat16 hy = __float2bfloat16(y);
    lo = pack_bf2(__float2bfloat16(x - __bfloat162float(hx)),
                  __float2bfloat16(y - __bfloat162float(hy)));
    return pack_bf2(hx, hy);
}
__device__ __forceinline__ void cp16(u32 smem, const void* g) {
    asm volatile("cp.async.cg.shared.global [%0], [%1], 16;" :: "r"(smem), "l"(g));
}
#define CP_COMMIT() asm volatile("cp.async.commit_group;" ::: "memory")
#define CP_WAIT(n)  asm volatile("cp.async.wait_group %0;" :: "n"(n) : "memory")

// ================= scratch ========================================================
__device__ float g_cos[Tt * 64];
__device__ float g_sin[Tt * 64];
__device__ __nv_bfloat16 g_xh[BT * Cc],  g_xl[BT * Cc];
__device__ __nv_bfloat16 g_wqh[Cc * Cc], g_wql[Cc * Cc];
__device__ __nv_bfloat16 g_wkh[Cc * Cc], g_wkl[Cc * Cc];
__device__ __nv_bfloat16 g_wvh[Cc * Cc], g_wvl[Cc * Cc];
__device__ __nv_bfloat16 g_woh[Cc * Cc], g_wol[Cc * Cc];
__device__ __nv_bfloat16 g_yh[BT * Cc],  g_yl[BT * Cc];
__device__ __nv_bfloat16 g_qhb[BT * Cc], g_qlb[BT * Cc];
__device__ __nv_bfloat16 g_khb[BT * Cc], g_klb[BT * Cc];
__device__ __nv_bfloat16 g_vth[32 * 128 * Tt], g_vtl[32 * 128 * Tt];

// ================= fp32 -> bf16 hi/lo split (all 5 inputs in one launch) ==========
__device__ __forceinline__ void split_store4(const float* src, __nv_bfloat16* hi,
                                             __nv_bfloat16* lo, int i)
{
    float4 v = *(const float4*)(src + i);
    __nv_bfloat16 h0 = __float2bfloat16(v.x);
    __nv_bfloat16 h1 = __float2bfloat16(v.y);
    __nv_bfloat16 h2 = __float2bfloat16(v.z);
    __nv_bfloat16 h3 = __float2bfloat16(v.w);
    __nv_bfloat162 H0; H0.x = h0; H0.y = h1;
    __nv_bfloat162 H1; H1.x = h2; H1.y = h3;
    *(__nv_bfloat162*)(hi + i)     = H0;
    *(__nv_bfloat162*)(hi + i + 2) = H1;
    __nv_bfloat162 L0, L1;
    L0.x = __float2bfloat16(v.x - __bfloat162float(h0));
    L0.y = __float2bfloat16(v.y - __bfloat162float(h1));
    L1.x = __float2bfloat16(v.z - __bfloat162float(h2));
    L1.y = __float2bfloat16(v.w - __bfloat162float(h3));
    *(__nv_bfloat162*)(lo + i)     = L0;
    *(__nv_bfloat162*)(lo + i + 2) = L1;
}

__global__ void __launch_bounds__(256)
conv_all(const float* x, const float* Wq, const float* Wk,
         const float* Wv, const float* Wo)
{
    int i = (blockIdx.x * blockDim.x + threadIdx.x) * 4;
    switch (blockIdx.z) {
        case 0: split_store4(x,  g_xh,  g_xl,  i); break;
        case 1: split_store4(Wq, g_wqh, g_wql, i); break;
        case 2: split_store4(Wk, g_wkh, g_wkl, i); break;
        case 3: split_store4(Wv, g_wvh, g_wvl, i); break;
        default: split_store4(Wo, g_woh, g_wol, i); break;
    }
}

// ================= HMMA split-bf16 NT GEMM mainloop (R12/R14-verified) ============
#define SROW 40
#define MATB (128 * SROW * 2)
#define BUFB (4 * MATB)
#define GEMM_SMEM (2 * BUFB)
#define CT_PITCH 133                           // fp32 staging tile pitch

// mainloop computes c[2][8][4] for warp tile 32x64 inside 128x128 CTA tile
__device__ __forceinline__ void gemm_mainloop(
    const __nv_bfloat16* __restrict__ Ah, const __nv_bfloat16* __restrict__ Al,
    const __nv_bfloat16* __restrict__ Bh, const __nv_bfloat16* __restrict__ Bl,
    char* sb, u32 sb32, int bm, int bn, float c[2][8][4])
{
    const int tid = threadIdx.x;
    const int wid = tid >> 5;
    const int lane = tid & 31;
    const int m0 = (wid >> 1) * 32;
    const int n0 = (wid & 1) * 64;

#pragma unroll
    for (int i = 0; i < 2; i++)
#pragma unroll
        for (int j = 0; j < 8; j++)
#pragma unroll
            for (int q = 0; q < 4; q++) c[i][j][q] = 0.f;

    const int lrow = tid >> 1;
    const int lhalf = (tid & 1) * 16;
    const size_t gA = (size_t)(bm + lrow) * 2048 + lhalf;
    const size_t gB = (size_t)(bn + lrow) * 2048 + lhalf;
    const u32 sOff = (u32)(lrow * (SROW * 2) + lhalf * 2);

    const u32 aRow = (u32)((lane & 7) + ((lane >> 3) & 1) * 8);
    const u32 aCol = (u32)(((lane >> 4) & 1) * 16);
    const u32 bRow = (u32)((lane & 7) + ((lane >> 4) & 1) * 8);
    const u32 bCol = (u32)(((lane >> 3) & 1) * 16);

    uint4 pf[8];
#pragma unroll
    for (int m = 0; m < 2; m++) {
        pf[0 + m] = *(const uint4*)(Ah + gA + m * 8);
        pf[2 + m] = *(const uint4*)(Al + gA + m * 8);
        pf[4 + m] = *(const uint4*)(Bh + gB + m * 8);
        pf[6 + m] = *(const uint4*)(Bl + gB + m * 8);
    }

    for (int k0 = 0; k0 < 2048; k0 += 32) {
        const u32 buf = ((u32)(k0 >> 5) & 1) * BUFB;

#pragma unroll
        for (int m = 0; m < 2; m++) {
            *(uint4*)(sb + buf + 0 * MATB + sOff + m * 16) = pf[0 + m];
            *(uint4*)(sb + buf + 1 * MATB + sOff + m * 16) = pf[2 + m];
            *(uint4*)(sb + buf + 2 * MATB + sOff + m * 16) = pf[4 + m];
            *(uint4*)(sb + buf + 3 * MATB + sOff + m * 16) = pf[6 + m];
        }
        __syncthreads();

        if (k0 + 32 < 2048) {
#pragma unroll
            for (int m = 0; m < 2; m++) {
                pf[0 + m] = *(const uint4*)(Ah + gA + k0 + 32 + m * 8);
                pf[2 + m] = *(const uint4*)(Al + gA + k0 + 32 + m * 8);
                pf[4 + m] = *(const uint4*)(Bh + gB + k0 + 32 + m * 8);
                pf[6 + m] = *(const uint4*)(Bl + gB + k0 + 32 + m * 8);
            }
        }

        const u32 baseAh = sb32 + buf;
        const u32 baseAl = baseAh + MATB;
        const u32 baseBh = baseAh + 2 * MATB;
        const u32 baseBl = baseAh + 3 * MATB;

#pragma unroll
        for (int s = 0; s < 2; s++) {
            const u32 kb = (u32)(s * 32);
            u32 ah[2][4], al[2][4], bh[4][4], bl[4][4];
#pragma unroll
            for (int mi = 0; mi < 2; mi++) {
                u32 ra = (u32)(m0 + mi * 16 + aRow) * (SROW * 2) + kb + aCol;
                ldsm_x4(ah[mi][0], ah[mi][1], ah[mi][2], ah[mi][3], baseAh + ra);
                ldsm_x4(al[mi][0], al[mi][1], al[mi][2], al[mi][3], baseAl + ra);
            }
#pragma unroll
            for (int np = 0; np < 4; np++) {
                u32 rb = (u32)(n0 + np * 16 + bRow) * (SROW * 2) + kb + bCol;
                ldsm_x4(bh[np][0], bh[np][1], bh[np][2], bh[np][3], baseBh + rb);
                ldsm_x4(bl[np][0], bl[np][1], bl[np][2], bl[np][3], baseBl + rb);
            }
#pragma unroll
            for (int mi = 0; mi < 2; mi++)
#pragma unroll
                for (int np = 0; np < 4; np++) {
                    mma16816(c[mi][np * 2 + 0], ah[mi], &bh[np][0]);
                    mma16816(c[mi][np * 2 + 1], ah[mi], &bh[np][2]);
                    mma16816(c[mi][np * 2 + 0], al[mi], &bh[np][0]);
                    mma16816(c[mi][np * 2 + 1], al[mi], &bh[np][2]);
                    mma16816(c[mi][np * 2 + 0], ah[mi], &bl[np][0]);
                    mma16816(c[mi][np * 2 + 1], ah[mi], &bl[np][2]);
                }
        }
        __syncthreads();
    }
}

// ---- out projection: plain fp32 epilogue -----------------------------------------
__global__ void __launch_bounds__(256, 1)
out_mma(float* __restrict__ out)
{
    extern __shared__ char sb[];
    const u32 sb32 = smem_u32_of(sb);
    const int bm = blockIdx.y * 128;
    const int bn = blockIdx.x * 128;
    float c[2][8][4];
    gemm_mainloop(g_yh, g_yl, g_woh, g_wol, sb, sb32, bm, bn, c);

    const int wid = threadIdx.x >> 5;
    const int lane = threadIdx.x & 31;
    const int m0 = (wid >> 1) * 32;
    const int n0 = (wid & 1) * 64;
    const int g  = lane >> 2;
    const int tg = (lane & 3) * 2;
#pragma unroll
    for (int mi = 0; mi < 2; mi++)
#pragma unroll
        for (int nj = 0; nj < 8; nj++) {
            int row = bm + m0 + mi * 16 + g;
            int col = bn + n0 + nj * 8 + tg;
            float* cp0 = out + (size_t)row * 2048 + col;
            float* cp1 = out + (size_t)(row + 8) * 2048 + col;
            *(float2*)cp0 = make_float2(c[mi][nj][0], c[mi][nj][1]);
            *(float2*)cp1 = make_float2(c[mi][nj][2], c[mi][nj][3]);
        }
}

// ---- qkv projection: fused rope/split/transpose epilogue --------------------------
// blockIdx.x = head h (n block), blockIdx.y = m block, blockIdx.z = 0:Q 1:K 2:V
__global__ void __launch_bounds__(256, 1)
qkv_mma()
{
    extern __shared__ char sb[];
    const u32 sb32 = smem_u32_of(sb);
    const int tid = threadIdx.x;
    const int bm = blockIdx.y * 128;
    const int h  = blockIdx.x;
    const int bn = h * 128;
    const int z  = blockIdx.z;

    const __nv_bfloat16 *Bh, *Bl;
    if (z == 0)      { Bh = g_wqh; Bl = g_wql; }
    else if (z == 1) { Bh = g_wkh; Bl = g_wkl; }
    else             { Bh = g_wvh; Bl = g_wvl; }

    float c[2][8][4];
    gemm_mainloop(g_xh, g_xl, Bh, Bl, sb, sb32, bm, bn, c);

    // stage C tile into smem fp32 [128][CT_PITCH]
    float* ct = (float*)sb;
    {
        const int wid = tid >> 5;
        const int lane = tid & 31;
        const int m0 = (wid >> 1) * 32;
        const int n0 = (wid & 1) * 64;
        const int g  = lane >> 2;
        const int tg = (lane & 3) * 2;
#pragma unroll
        for (int mi = 0; mi < 2; mi++)
#pragma unroll
            for (int nj = 0; nj < 8; nj++) {
                int row = m0 + mi * 16 + g;
                int col = n0 + nj * 8 + tg;
                ct[row * CT_PITCH + col]           = c[mi][nj][0];
                ct[row * CT_PITCH + col + 1]       = c[mi][nj][1];
                ct[(row + 8) * CT_PITCH + col]     = c[mi][nj][2];
                ct[(row + 8) * CT_PITCH + col + 1] = c[mi][nj][3];
            }
    }
    __syncthreads();

    if (z < 2) {
        // rope (+scale for Q), split, write [bt][2048] bf16
        const float scale = (z == 0) ? 0.08838834764831845f : 1.0f;
        __nv_bfloat16* hb = (z == 0) ? g_qhb : g_khb;
        __nv_bfloat16* lb = (z == 0) ? g_qlb : g_klb;
#pragma unroll
        for (int it = 0; it < 32; it++) {
            int idx = tid + it * 256;          // 128*64 = 8192
            int r = idx >> 6, j = idx & 63;
            int t = (bm + r) & (Tt - 1);
            float cth = g_cos[t * 64 + j];
            float sth = g_sin[t * 64 + j];
            float a0 = ct[r * CT_PITCH + j];
            float a1 = ct[r * CT_PITCH + j + 64];
            float r0 = (a0 * cth + a1 * sth) * scale;
            float r1 = (a1 * cth - a0 * sth) * scale;
            __nv_bfloat16 h0 = __float2bfloat16(r0);
            __nv_bfloat16 h1 = __float2bfloat16(r1);
            size_t base = (size_t)(bm + r) * 2048 + (size_t)h * 128 + j;
            hb[base]      = h0;
            hb[base + 64] = h1;
            lb[base]      = __float2bfloat16(r0 - __bfloat162float(h0));
            lb[base + 64] = __float2bfloat16(r1 - __bfloat162float(h1));
        }
    } else {
        // V: transpose to [bh][d][t], split, write u32 pairs
        const int b = bm >> 10;
        const int tb = bm & (Tt - 1);
        __nv_bfloat16* oh = g_vth + (size_t)(b * 16 + h) * 128 * Tt + tb;
        __nv_bfloat16* ol = g_vtl + (size_t)(b * 16 + h) * 128 * Tt + tb;
#pragma unroll
        for (int it = 0; it < 32; it++) {
            int idx = tid + it * 256;          // 128 d * 64 t-pairs = 8192
            int d = idx >> 6, tp = (idx & 63) * 2;
            float v0 = ct[tp * CT_PITCH + d];
            float v1 = ct[(tp + 1) * CT_PITCH + d];
            u32 lo;
            u32 hi = split2(v0, v1, lo);
            *(u32*)(oh + (size_t)d * Tt + tp) = hi;
            *(u32*)(ol + (size_t)d * Tt + tp) = lo;
        }
    }
}

// ================= RoPE cos/sin table =============================================
__global__ void cs_table_kernel()
{
    int idx = blockIdx.x * blockDim.x + threadIdx.x;
    if (idx >= Tt * 64) return;
    int t = idx >> 6;
    int j = idx & 63;
    float invf = (float)exp(-((double)(2 * j) / 128.0) * log(10000.0));
    float thf  = (float)t * invf;
    double cd, sd;
    sincos((double)thf, &cd, &sd);
    g_cos[idx] = (float)cd;
    g_sin[idx] = (float)sd;
}

// ================= HMMA flash attention, double-buffered cp.async (R14) ===========
#define QROW 136
#define VROW 72
#define KB_KH 0
#define KB_KL (64 * QROW * 2)
#define KB_VH (2 * 64 * QROW * 2)
#define KB_VL (KB_VH + 128 * VROW * 2)
#define KVBUF (KB_VL + 128 * VROW * 2)
#define QH_OFF 0
#define QL_OFF (128 * QROW * 2)
#define FA_SMEM (2 * KVBUF)

__device__ __forceinline__ void fa_stage(
    char* dst, const __nv_bfloat16* khp, const __nv_bfloat16* klp,
    const __nv_bfloat16* vthp, const __nv_bfloat16* vtlp, int kbase, int tid)
{
    const u32 d32 = smem_u32_of(dst);
#pragma unroll
    for (int it = 0; it < 4; it++) {
        int idx = tid + it * 256;
        int r = idx >> 4, cc = idx & 15;
        size_t gk = (size_t)(kbase + r) * 2048 + cc * 8;
        u32 so = (u32)(r * QROW + cc * 8) * 2;
        cp16(d32 + KB_KH + so, khp + gk);
        cp16(d32 + KB_KL + so, klp + gk);
    }
#pragma unroll
    for (int it = 0; it < 4; it++) {
        int idx = tid + it * 256;
        int d = idx >> 3, cc = idx & 7;
        size_t gv = (size_t)d * Tt + kbase + cc * 8;
        u32 so = (u32)(d * VROW + cc * 8) * 2;
        cp16(d32 + KB_VH + so, vthp + gv);
        cp16(d32 + KB_VL + so, vtlp + gv);
    }
}

__global__ void __launch_bounds__(256, 1)
flash_mma()
{
    extern __shared__ char sb[];
    const u32 sb32 = smem_u32_of(sb);

    const int tid = threadIdx.x;
    const int wid = tid >> 5;
    const int lane = tid & 31;
    const int qt = 7 - blockIdx.x;
    const int bh = blockIdx.y;
    const int b = bh >> 4, h = bh & 15;
    const int qbase = qt * 128;

    const u32 aRow = (u32)((lane & 7) + ((lane >> 3) & 1) * 8);
    const u32 aCol = (u32)(((lane >> 4) & 1) * 16);
    const u32 bRow = (u32)((lane & 7) + ((lane >> 4) & 1) * 8);
    const u32 bCol = (u32)(((lane >> 3) & 1) * 16);
    const int g  = lane >> 2;
    const int t2 = (lane & 3) * 2;

    const __nv_bfloat16* qhp = g_qhb + (size_t)b * Tt * 2048 + (size_t)h * 128;
    const __nv_bfloat16* qlp = g_qlb + (size_t)b * Tt * 2048 + (size_t)h * 128;
    const __nv_bfloat16* khp = g_khb + (size_t)b * Tt * 2048 + (size_t)h * 128;
    const __nv_bfloat16* klp = g_klb + (size_t)b * Tt * 2048 + (size_t)h * 128;
    const __nv_bfloat16* vthp = g_vth + (size_t)bh * 128 * Tt;
    const __nv_bfloat16* vtlp = g_vtl + (size_t)bh * 128 * Tt;

    for (int idx = tid; idx < 128 * 16; idx += 256) {
        int r = idx >> 4, cc = idx & 15;
        size_t gq = (size_t)(qbase + r) * 2048 + cc * 8;
        u32 so = (u32)(r * QROW + cc * 8) * 2;
        *(uint4*)(sb + QH_OFF + so) = *(const uint4*)(qhp + gq);
        *(uint4*)(sb + QL_OFF + so) = *(const uint4*)(qlp + gq);
    }
    __syncthreads();

    u32 qh[8][4], ql[8][4];
#pragma unroll
    for (int ks = 0; ks < 8; ks++) {
        u32 ra = (u32)(wid * 16 + aRow) * (QROW * 2) + (u32)ks * 32 + aCol;
        ldsm_x4(qh[ks][0], qh[ks][1], qh[ks][2], qh[ks][3], sb32 + QH_OFF + ra);
        ldsm_x4(ql[ks][0], ql[ks][1], ql[ks][2], ql[ks][3], sb32 + QL_OFF + ra);
    }
    __syncthreads();

    float o[16][4];
#pragma unroll
    for (int i = 0; i < 16; i++)
#pragma unroll
        for (int q = 0; q < 4; q++) o[i][q] = 0.f;
    float m0 = -1e30f, m1 = -1e30f, l0 = 0.f, l1 = 0.f;

    const int nkv = 2 * qt + 2;

    fa_stage(sb, khp, klp, vthp, vtlp, 0, tid);
    CP_COMMIT();

    for (int kt = 0; kt < nkv; kt++) {
        const int kbase = kt * 64;

        if (kt + 1 < nkv)
            fa_stage(sb + ((kt + 1) & 1) * KVBUF, khp, klp, vthp, vtlp,
                     (kt + 1) * 64, tid);
        CP_COMMIT();
        CP_WAIT(1);
        __syncthreads();

        const u32 base = sb32 + (u32)(kt & 1) * KVBUF;

        float sf[8][4];
#pragma unroll
        for (int i = 0; i < 8; i++)
#pragma unroll
            for (int q = 0; q < 4; q++) sf[i][q] = 0.f;

#pragma unroll
        for (int np = 0; np < 4; np++)
#pragma unroll
            for (int ks = 0; ks < 8; ks++) {
                u32 rb = (u32)(np * 16 + bRow) * (QROW * 2) + (u32)ks * 32 + bCol;
                u32 kh[4], kl[4];
                ldsm_x4(kh[0], kh[1], kh[2], kh[3], base + KB_KH + rb);
                ldsm_x4(kl[0], kl[1], kl[2], kl[3], base + KB_KL + rb);
                mma16816(sf[np * 2 + 0], qh[ks], &kh[0]);
                mma16816(sf[np * 2 + 1], qh[ks], &kh[2]);
                mma16816(sf[np * 2 + 0], ql[ks], &kh[0]);
                mma16816(sf[np * 2 + 1], ql[ks], &kh[2]);
                mma16816(sf[np * 2 + 0], qh[ks], &kl[0]);
                mma16816(sf[np * 2 + 1], qh[ks], &kl[2]);
            }

        const int row0 = qbase + wid * 16 + g;
        const int row1 = row0 + 8;
        if (kbase + 63 > qbase + wid * 16) {
#pragma unroll
            for (int nt = 0; nt < 8; nt++) {
                int col = kbase + nt * 8 + t2;
                if (col     > row0) sf[nt][0] = -1e30f;
                if (col + 1 > row0) sf[nt][1] = -1e30f;
                if (col     > row1) sf[nt][2] = -1e30f;
                if (col + 1 > row1) sf[nt][3] = -1e30f;
            }
        }

        float mx0 = -1e30f, mx1 = -1e30f;
#pragma unroll
        for (int nt = 0; nt < 8; nt++) {
            mx0 = fmaxf(mx0, fmaxf(sf[nt][0], sf[nt][1]));
            mx1 = fmaxf(mx1, fmaxf(sf[nt][2], sf[nt][3]));
        }
        mx0 = fmaxf(mx0, __shfl_xor_sync(0xffffffffu, mx0, 1));
        mx0 = fmaxf(mx0, __shfl_xor_sync(0xffffffffu, mx0, 2));
        mx1 = fmaxf(mx1, __shfl_xor_sync(0xffffffffu, mx1, 1));
        mx1 = fmaxf(mx1, __shfl_xor_sync(0xffffffffu, mx1, 2));
        float mn0 = fmaxf(m0, mx0);
        float mn1 = fmaxf(m1, mx1);
        float s0 = 0.f, s1 = 0.f;
#pragma unroll
        for (int nt = 0; nt < 8; nt++) {
            sf[nt][0] = __expf(sf[nt][0] - mn0);
            sf[nt][1] = __expf(sf[nt][1] - mn0);
            sf[nt][2] = __expf(sf[nt][2] - mn1);
            sf[nt][3] = __expf(sf[nt][3] - mn1);
            s0 += sf[nt][0] + sf[nt][1];
            s1 += sf[nt][2] + sf[nt][3];
        }
        s0 += __shfl_xor_sync(0xffffffffu, s0, 1);
        s0 += __shfl_xor_sync(0xffffffffu, s0, 2);
        s1 += __shfl_xor_sync(0xffffffffu, s1, 1);
        s1 += __shfl_xor_sync(0xffffffffu, s1, 2);
        float al0 = __expf(m0 - mn0);
        float al1 = __expf(m1 - mn1);
        l0 = l0 * al0 + s0;  m0 = mn0;
        l1 = l1 * al1 + s1;  m1 = mn1;
#pragma unroll
        for (int nt = 0; nt < 16; nt++) {
            o[nt][0] *= al0; o[nt][1] *= al0;
            o[nt][2] *= al1; o[nt][3] *= al1;
        }

        u32 ph[4][4], pl[4][4];
#pragma unroll
        for (int j = 0; j < 4; j++) {
            ph[j][0] = split2(sf[2 * j][0],     sf[2 * j][1],     pl[j][0]);
            ph[j][1] = split2(sf[2 * j][2],     sf[2 * j][3],     pl[j][1]);
            ph[j][2] = split2(sf[2 * j + 1][0], sf[2 * j + 1][1], pl[j][2]);
            ph[j][3] = split2(sf[2 * j + 1][2], sf[2 * j + 1][3], pl[j][3]);
        }

#pragma unroll
        for (int np = 0; np < 8; np++)
#pragma unroll
            for (int ks = 0; ks < 4; ks++) {
                u32 rb = (u32)(np * 16 + bRow) * (VROW * 2) + (u32)ks * 32 + bCol;
                u32 vh[4], vl[4];
                ldsm_x4(vh[0], vh[1], vh[2], vh[3], base + KB_VH + rb);
                ldsm_x4(vl[0], vl[1], vl[2], vl[3], base + KB_VL + rb);
                mma16816(o[np * 2 + 0], ph[ks], &vh[0]);
                mma16816(o[np * 2 + 1], ph[ks], &vh[2]);
                mma16816(o[np * 2 + 0], pl[ks], &vh[0]);
                mma16816(o[np * 2 + 1], pl[ks], &vh[2]);
                mma16816(o[np * 2 + 0], ph[ks], &vl[0]);
                mma16816(o[np * 2 + 1], ph[ks], &vl[2]);
            }
        __syncthreads();
    }

    float inv0 = 1.0f / l0;
    float inv1 = 1.0f / l1;
    __nv_bfloat16* yhp = g_yh + (size_t)b * Tt * 2048 + (size_t)h * 128;
    __nv_bfloat16* ylp = g_yl + (size_t)b * Tt * 2048 + (size_t)h * 128;
#pragma unroll
    for (int nt = 0; nt < 16; nt++) {
        int row = qbase + wid * 16 + g;
        int col = nt * 8 + t2;
        u32 lo0, lo1;
        u32 hi0 = split2(o[nt][0] * inv0, o[nt][1] * inv0, lo0);
        u32 hi1 = split2(o[nt][2] * inv1, o[nt][3] * inv1, lo1);
        *(u32*)(yhp + (size_t)row * 2048 + col)       = hi0;
        *(u32*)(ylp + (size_t)row * 2048 + col)       = lo0;
        *(u32*)(yhp + (size_t)(row + 8) * 2048 + col) = hi1;
        *(u32*)(ylp + (size_t)(row + 8) * 2048 + col) = lo1;
    }
}

// ================= launch =========================================================
extern "C" void kernel_launch(void* const* d_in, const int* in_sizes, int n_in,
                              void* d_out, int out_size)
{
    (void)in_sizes; (void)n_in; (void)out_size;
    const float* x  = (const float*)d_in[0];
    const float* Wq = (const float*)d_in[1];
    const float* Wk = (const float*)d_in[2];
    const float* Wv = (const float*)d_in[3];
    const float* Wo = (const float*)d_in[4];
    float* out = (float*)d_out;

    cudaFuncSetAttribute(flash_mma, cudaFuncAttributeMaxDynamicSharedMemorySize, FA_SMEM);
    cudaFuncSetAttribute(qkv_mma,   cudaFuncAttributeMaxDynamicSharedMemorySize, GEMM_SMEM);
    cudaFuncSetAttribute(out_mma,   cudaFuncAttributeMaxDynamicSharedMemorySize, GEMM_SMEM);

    const int CONV_BLKS = (BT * Cc / 4) / 256;

    cs_table_kernel<<<(Tt * 64) / 256, 256>>>();                      // 1
    conv_all<<<dim3(CONV_BLKS, 1, 5), 256>>>(x, Wq, Wk, Wv, Wo);      // 2
    qkv_mma<<<dim3(16, 16, 3), 256, GEMM_SMEM>>>();                   // 3
    flash_mma<<<dim3(8, 32), 256, FA_SMEM>>>();                       // 4
    out_mma<<<dim3(16, 16), 256, GEMM_SMEM>>>(out);                   // 5
}

// round 16
// speedup vs baseline: 1.4662x; 1.4662x over previous
#include <cuda_runtime.h>
#include <cuda_fp16.h>
#include <math.h>

#define Bb 2
#define Tt 1024
#define Cc 2048
#define Hh 16
#define Dd 128
#define BT (Bb*Tt)

typedef unsigned long long u64;
typedef unsigned int u32;

// ================= portable tensor-core helpers (fp16 HMMA) =======================
__device__ __forceinline__ u32 smem_u32_of(const void* p) {
    u32 a; asm("{ .reg .u64 t; cvta.to.shared.u64 t, %1; cvt.u32.u64 %0, t; }"
               : "=r"(a) : "l"(p));
    return a;
}
__device__ __forceinline__ void ldsm_x4(u32& r0, u32& r1, u32& r2, u32& r3, u32 addr) {
    asm volatile("ldmatrix.sync.aligned.m8n8.x4.shared.b16 {%0,%1,%2,%3}, [%4];"
                 : "=r"(r0), "=r"(r1), "=r"(r2), "=r"(r3) : "r"(addr));
}
__device__ __forceinline__ void mma16816(float* c, const u32* a, const u32* b) {
    asm volatile(
        "mma.sync.aligned.m16n8k16.row.col.f32.f16.f16.f32 "
        "{%0,%1,%2,%3}, {%4,%5,%6,%7}, {%8,%9}, {%0,%1,%2,%3};"
        : "+f"(c[0]), "+f"(c[1]), "+f"(c[2]), "+f"(c[3])
        : "r"(a[0]), "r"(a[1]), "r"(a[2]), "r"(a[3]), "r"(b[0]), "r"(b[1]));
}
__device__ __forceinline__ u32 pack_h2(__half x, __half y) {
    __half2 t; t.x = x; t.y = y;
    return *(u32*)&t;
}
// split two floats into fp16-hi pair (returned) and fp16-residual pair (out)
__device__ __forceinline__ u32 split2(float x, float y, u32& lo) {
    __half hx = __float2half_rn(x);
    __half hy = __float2half_rn(y);
    lo = pack_h2(__float2half_rn(x - __half2float(hx)),
                 __float2half_rn(y - __half2float(hy)));
    return pack_h2(hx, hy);
}
__device__ __forceinline__ void cp16(u32 smem, const void* g) {
    asm volatile("cp.async.cg.shared.global [%0], [%1], 16;" :: "r"(smem), "l"(g));
}
#define CP_COMMIT() asm volatile("cp.async.commit_group;" ::: "memory")
#define CP_WAIT(n)  asm volatile("cp.async.wait_group %0;" :: "n"(n) : "memory")

// ================= scratch ========================================================
__device__ float g_q[BT * Cc];
__device__ float g_k[BT * Cc];
__device__ float g_v[BT * Cc];
__device__ float g_cos[Tt * 64];
__device__ float g_sin[Tt * 64];
__device__ __half g_xh[BT * Cc],  g_xl[BT * Cc];
__device__ __half g_wqh[Cc * Cc];           // weights: hi only (2-term split)
__device__ __half g_wkh[Cc * Cc];
__device__ __half g_wvh[Cc * Cc];
__device__ __half g_woh[Cc * Cc];
__device__ __half g_yh[BT * Cc],  g_yl[BT * Cc];
__device__ __half g_qhb[BT * Cc], g_qlb[BT * Cc];
__device__ __half g_khb[BT * Cc];           // K: hi only (B side of S = Q K^T)
__device__ __half g_vth[32 * 128 * Tt];     // Vt: hi only (B side of P V)

// ================= fp32 -> fp16 conversions (one launch) ==========================
__device__ __forceinline__ void split_store4(const float* src, __half* hi,
                                             __half* lo, int i)
{
    float4 v = *(const float4*)(src + i);
    __half h0 = __float2half_rn(v.x);
    __half h1 = __float2half_rn(v.y);
    __half h2 = __float2half_rn(v.z);
    __half h3 = __float2half_rn(v.w);
    *(u32*)(hi + i)     = pack_h2(h0, h1);
    *(u32*)(hi + i + 2) = pack_h2(h2, h3);
    *(u32*)(lo + i)     = pack_h2(__float2half_rn(v.x - __half2float(h0)),
                                  __float2half_rn(v.y - __half2float(h1)));
    *(u32*)(lo + i + 2) = pack_h2(__float2half_rn(v.z - __half2float(h2)),
                                  __float2half_rn(v.w - __half2float(h3)));
}
__device__ __forceinline__ void hi_store4(const float* src, __half* hi, int i)
{
    float4 v = *(const float4*)(src + i);
    *(u32*)(hi + i)     = pack_h2(__float2half_rn(v.x), __float2half_rn(v.y));
    *(u32*)(hi + i + 2) = pack_h2(__float2half_rn(v.z), __float2half_rn(v.w));
}

__global__ void __launch_bounds__(256)
conv_all(const float* x, const float* Wq, const float* Wk,
         const float* Wv, const float* Wo)
{
    int i = (blockIdx.x * blockDim.x + threadIdx.x) * 4;
    switch (blockIdx.z) {
        case 0: split_store4(x, g_xh, g_xl, i); break;
        case 1: hi_store4(Wq, g_wqh, i); break;
        case 2: hi_store4(Wk, g_wkh, i); break;
        case 3: hi_store4(Wv, g_wvh, i); break;
        default: hi_store4(Wo, g_woh, i); break;
    }
}

// ================= HMMA 2-term fp16 NT GEMM: C = (Ah+Al) @ Bh^T ===================
#define SROW 40
#define MATB (128 * SROW * 2)                // 10240
#define BUFB (3 * MATB)                      // Ah, Al, Bh
#define GEMM_SMEM (2 * BUFB)                 // 61440

__device__ __forceinline__ void mma_gemm_body(
    const __half* __restrict__ Ah, const __half* __restrict__ Al,
    const __half* __restrict__ Bh, float* __restrict__ Cout)
{
    extern __shared__ char sb[];
    const u32 sb32 = smem_u32_of(sb);

    const int tid = threadIdx.x;
    const int wid = tid >> 5;
    const int lane = tid & 31;
    const int bm = blockIdx.y * 128;
    const int bn = blockIdx.x * 128;
    const int m0 = (wid >> 1) * 32;
    const int n0 = (wid & 1) * 64;

    float c[2][8][4];
#pragma unroll
    for (int i = 0; i < 2; i++)
#pragma unroll
        for (int j = 0; j < 8; j++)
#pragma unroll
            for (int q = 0; q < 4; q++) c[i][j][q] = 0.f;

    const int lrow = tid >> 1;
    const int lhalf = (tid & 1) * 16;
    const size_t gA = (size_t)(bm + lrow) * 2048 + lhalf;
    const size_t gB = (size_t)(bn + lrow) * 2048 + lhalf;
    const u32 sOff = (u32)(lrow * (SROW * 2) + lhalf * 2);

    const u32 aRow = (u32)((lane & 7) + ((lane >> 3) & 1) * 8);
    const u32 aCol = (u32)(((lane >> 4) & 1) * 16);
    const u32 bRow = (u32)((lane & 7) + ((lane >> 4) & 1) * 8);
    const u32 bCol = (u32)(((lane >> 3) & 1) * 16);

    uint4 pf[6];
#pragma unroll
    for (int m = 0; m < 2; m++) {
        pf[0 + m] = *(const uint4*)(Ah + gA + m * 8);
        pf[2 + m] = *(const uint4*)(Al + gA + m * 8);
        pf[4 + m] = *(const uint4*)(Bh + gB + m * 8);
    }

    for (int k0 = 0; k0 < 2048; k0 += 32) {
        const u32 buf = ((u32)(k0 >> 5) & 1) * BUFB;

#pragma unroll
        for (int m = 0; m < 2; m++) {
            *(uint4*)(sb + buf + 0 * MATB + sOff + m * 16) = pf[0 + m];
            *(uint4*)(sb + buf + 1 * MATB + sOff + m * 16) = pf[2 + m];
            *(uint4*)(sb + buf + 2 * MATB + sOff + m * 16) = pf[4 + m];
        }
        __syncthreads();

        if (k0 + 32 < 2048) {
#pragma unroll
            for (int m = 0; m < 2; m++) {
                pf[0 + m] = *(const uint4*)(Ah + gA + k0 + 32 + m * 8);
                pf[2 + m] = *(const uint4*)(Al + gA + k0 + 32 + m * 8);
                pf[4 + m] = *(const uint4*)(Bh + gB + k0 + 32 + m * 8);
            }
        }

        const u32 baseAh = sb32 + buf;
        const u32 baseAl = baseAh + MATB;
        const u32 baseBh = baseAh + 2 * MATB;

#pragma unroll
        for (int s = 0; s < 2; s++) {
            const u32 kb = (u32)(s * 32);
            u32 ah[2][4], al[2][4], bh[4][4];
#pragma unroll
            for (int mi = 0; mi < 2; mi++) {
                u32 ra = (u32)(m0 + mi * 16 + aRow) * (SROW * 2) + kb + aCol;
                ldsm_x4(ah[mi][0], ah[mi][1], ah[mi][2], ah[mi][3], baseAh + ra);
                ldsm_x4(al[mi][0], al[mi][1], al[mi][2], al[mi][3], baseAl + ra);
            }
#pragma unroll
            for (int np = 0; np < 4; np++) {
                u32 rb = (u32)(n0 + np * 16 + bRow) * (SROW * 2) + kb + bCol;
                ldsm_x4(bh[np][0], bh[np][1], bh[np][2], bh[np][3], baseBh + rb);
            }
#pragma unroll
            for (int mi = 0; mi < 2; mi++)
#pragma unroll
                for (int np = 0; np < 4; np++) {
                    mma16816(c[mi][np * 2 + 0], ah[mi], &bh[np][0]);
                    mma16816(c[mi][np * 2 + 1], ah[mi], &bh[np][2]);
                    mma16816(c[mi][np * 2 + 0], al[mi], &bh[np][0]);
                    mma16816(c[mi][np * 2 + 1], al[mi], &bh[np][2]);
                }
        }
        __syncthreads();
    }

    const int g  = lane >> 2;
    const int tg = (lane & 3) * 2;
#pragma unroll
    for (int mi = 0; mi < 2; mi++)
#pragma unroll
        for (int nj = 0; nj < 8; nj++) {
            int row = bm + m0 + mi * 16 + g;
            int col = bn + n0 + nj * 8 + tg;
            float* cp0 = Cout + (size_t)row * 2048 + col;
            float* cp1 = Cout + (size_t)(row + 8) * 2048 + col;
            *(float2*)cp0 = make_float2(c[mi][nj][0], c[mi][nj][1]);
            *(float2*)cp1 = make_float2(c[mi][nj][2], c[mi][nj][3]);
        }
}

__global__ void __launch_bounds__(256, 1)
qkv_mma()
{
    const __half* Bh; float* out;
    if (blockIdx.z == 0)      { Bh = g_wqh; out = g_q; }
    else if (blockIdx.z == 1) { Bh = g_wkh; out = g_k; }
    else                      { Bh = g_wvh; out = g_v; }
    mma_gemm_body(g_xh, g_xl, Bh, out);
}

__global__ void __launch_bounds__(256, 1)
out_mma(float* __restrict__ out)
{
    mma_gemm_body(g_yh, g_yl, g_woh, out);
}

// ================= RoPE cos/sin table =============================================
__global__ void cs_table_kernel()
{
    int idx = blockIdx.x * blockDim.x + threadIdx.x;
    if (idx >= Tt * 64) return;
    int t = idx >> 6;
    int j = idx & 63;
    float invf = (float)exp(-((double)(2 * j) / 128.0) * log(10000.0));
    float thf  = (float)t * invf;
    double cd, sd;
    sincos((double)thf, &cd, &sd);
    g_cos[idx] = (float)cd;
    g_sin[idx] = (float)sd;
}

// ================= prep: rope q/k -> fp16 (Q split 2-term, K hi only) =============
// NOTE: scale is NOT folded into Q (applied to S in fp32) to keep residuals normal.
__global__ void __launch_bounds__(256)
prep_qk()
{
    int idx = blockIdx.x * blockDim.x + threadIdx.x;
    int j   = idx & 63;
    int h   = (idx >> 6) & 15;
    int row = idx >> 10;
    int t   = row & (Tt - 1);

    float c = g_cos[t * 64 + j];
    float s = g_sin[t * 64 + j];
    size_t base = (size_t)row * 2048 + (size_t)h * 128 + j;

    {
        float a0 = g_q[base], a1 = g_q[base + 64];
        float r0 = a0 * c + a1 * s;
        float r1 = a1 * c - a0 * s;
        __half h0 = __float2half_rn(r0);
        __half h1 = __float2half_rn(r1);
        g_qhb[base]      = h0;
        g_qhb[base + 64] = h1;
        g_qlb[base]      = __float2half_rn(r0 - __half2float(h0));
        g_qlb[base + 64] = __float2half_rn(r1 - __half2float(h1));
    }
    {
        float a0 = g_k[base], a1 = g_k[base + 64];
        g_khb[base]      = __float2half_rn(a0 * c + a1 * s);
        g_khb[base + 64] = __float2half_rn(a1 * c - a0 * s);
    }
}

// ================= prep: transpose V -> [bh][d][t] fp16 hi ========================
__global__ void __launch_bounds__(256)
prep_vt()
{
    __shared__ float vs[128][65];
    const int tid = threadIdx.x;
    const int tt = blockIdx.x;
    const int bh = blockIdx.y;
    const int b = bh >> 4, h = bh & 15;
    const int tb = tt * 64;

    const float* vp = g_v + (size_t)b * Tt * Cc + (size_t)h * Dd;
    for (int e = tid; e < 64 * 128; e += 256) {
        int t = e >> 7, d = e & 127;
        vs[d][t] = vp[(size_t)(tb + t) * 2048 + d];
    }
    __syncthreads();

    __half* oh = g_vth + (size_t)bh * 128 * Tt + tb;
    for (int e = tid; e < 128 * 32; e += 256) {
        int d = e >> 5, tw = (e & 31) * 2;
        *(u32*)(oh + (size_t)d * Tt + tw) =
            pack_h2(__float2half_rn(vs[d][tw]), __float2half_rn(vs[d][tw + 1]));
    }
}

// ================= HMMA flash attention, fp16 2-term, cp.async ====================
#define QROW 136
#define VROW 72
#define KB_KH 0
#define KB_VH (64 * QROW * 2)                 // 17408
#define KVBUF (KB_VH + 128 * VROW * 2)        // 35840
#define QH_OFF 0
#define QL_OFF (128 * QROW * 2)               // Q total 69632 < 2*KVBUF
#define FA_SMEM (2 * KVBUF)                   // 71680

__device__ __forceinline__ void fa_stage(
    char* dst, const __half* khp, const __half* vthp, int kbase, int tid)
{
    const u32 d32 = smem_u32_of(dst);
#pragma unroll
    for (int it = 0; it < 4; it++) {
        int idx = tid + it * 256;             // 0..1023
        int r = idx >> 4, cc = idx & 15;
        size_t gk = (size_t)(kbase + r) * 2048 + cc * 8;
        cp16(d32 + KB_KH + (u32)(r * QROW + cc * 8) * 2, khp + gk);
    }
#pragma unroll
    for (int it = 0; it < 4; it++) {
        int idx = tid + it * 256;             // 0..1023
        int d = idx >> 3, cc = idx & 7;
        size_t gv = (size_t)d * Tt + kbase + cc * 8;
        cp16(d32 + KB_VH + (u32)(d * VROW + cc * 8) * 2, vthp + gv);
    }
}

__global__ void __launch_bounds__(256, 1)
flash_mma()
{
    extern __shared__ char sb[];
    const u32 sb32 = smem_u32_of(sb);

    const int tid = threadIdx.x;
    const int wid = tid >> 5;
    const int lane = tid & 31;
    const int qt = 7 - blockIdx.x;
    const int bh = blockIdx.y;
    const int b = bh >> 4, h = bh & 15;
    const int qbase = qt * 128;
    const float scale = 0.08838834764831845f;   // applied to S in fp32

    const u32 aRow = (u32)((lane & 7) + ((lane >> 3) & 1) * 8);
    const u32 aCol = (u32)(((lane >> 4) & 1) * 16);
    const u32 bRow = (u32)((lane & 7) + ((lane >> 4) & 1) * 8);
    const u32 bCol = (u32)(((lane >> 3) & 1) * 16);
    const int g  = lane >> 2;
    const int t2 = (lane & 3) * 2;

    const __half* qhp = g_qhb + (size_t)b * Tt * 2048 + (size_t)h * 128;
    const __half* qlp = g_qlb + (size_t)b * Tt * 2048 + (size_t)h * 128;
    const __half* khp = g_khb + (size_t)b * Tt * 2048 + (size_t)h * 128;
    const __half* vthp = g_vth + (size_t)bh * 128 * Tt;

    for (int idx = tid; idx < 128 * 16; idx += 256) {
        int r = idx >> 4, cc = idx & 15;
        size_t gq = (size_t)(qbase + r) * 2048 + cc * 8;
        u32 so = (u32)(r * QROW + cc * 8) * 2;
        *(uint4*)(sb + QH_OFF + so) = *(const uint4*)(qhp + gq);
        *(uint4*)(sb + QL_OFF + so) = *(const uint4*)(qlp + gq);
    }
    __syncthreads();

    u32 qh[8][4], ql[8][4];
#pragma unroll
    for (int ks = 0; ks < 8; ks++) {
        u32 ra = (u32)(wid * 16 + aRow) * (QROW * 2) + (u32)ks * 32 + aCol;
        ldsm_x4(qh[ks][0], qh[ks][1], qh[ks][2], qh[ks][3], sb32 + QH_OFF + ra);
        ldsm_x4(ql[ks][0], ql[ks][1], ql[ks][2], ql[ks][3], sb32 + QL_OFF + ra);
    }
    __syncthreads();   // Q region reused as KV buffers

    float o[16][4];
#pragma unroll
    for (int i = 0; i < 16; i++)
#pragma unroll
        for (int q = 0; q < 4; q++) o[i][q] = 0.f;
    float m0 = -1e30f, m1 = -1e30f, l0 = 0.f, l1 = 0.f;

    const int nkv = 2 * qt + 2;

    fa_stage(sb, khp, vthp, 0, tid);
    CP_COMMIT();

    for (int kt = 0; kt < nkv; kt++) {
        const int kbase = kt * 64;

        if (kt + 1 < nkv)
            fa_stage(sb + ((kt + 1) & 1) * KVBUF, khp, vthp, (kt + 1) * 64, tid);
        CP_COMMIT();
        CP_WAIT(1);
        __syncthreads();

        const u32 base = sb32 + (u32)(kt & 1) * KVBUF;

        // S = Q K^T (2-term fp16 split)
        float sf[8][4];
#pragma unroll
        for (int i = 0; i < 8; i++)
#pragma unroll
            for (int q = 0; q < 4; q++) sf[i][q] = 0.f;

#pragma unroll
        for (int np = 0; np < 4; np++)
#pragma unroll
            for (int ks = 0; ks < 8; ks++) {
                u32 rb = (u32)(np * 16 + bRow) * (QROW * 2) + (u32)ks * 32 + bCol;
                u32 kh[4];
                ldsm_x4(kh[0], kh[1], kh[2], kh[3], base + KB_KH + rb);
                mma16816(sf[np * 2 + 0], qh[ks], &kh[0]);
                mma16816(sf[np * 2 + 1], qh[ks], &kh[2]);
                mma16816(sf[np * 2 + 0], ql[ks], &kh[0]);
                mma16816(sf[np * 2 + 1], ql[ks], &kh[2]);
            }

        // fp32 scale, then causal mask
#pragma unroll
        for (int nt = 0; nt < 8; nt++) {
            sf[nt][0] *= scale; sf[nt][1] *= scale;
            sf[nt][2] *= scale; sf[nt][3] *= scale;
        }
        const int row0 = qbase + wid * 16 + g;
        const int row1 = row0 + 8;
        if (kbase + 63 > qbase + wid * 16) {
#pragma unroll
            for (int nt = 0; nt < 8; nt++) {
                int col = kbase + nt * 8 + t2;
                if (col     > row0) sf[nt][0] = -1e30f;
                if (col + 1 > row0) sf[nt][1] = -1e30f;
                if (col     > row1) sf[nt][2] = -1e30f;
                if (col + 1 > row1) sf[nt][3] = -1e30f;
            }
        }

        // online softmax
        float mx0 = -1e30f, mx1 = -1e30f;
#pragma unroll
        for (int nt = 0; nt < 8; nt++) {
            mx0 = fmaxf(mx0, fmaxf(sf[nt][0], sf[nt][1]));
            mx1 = fmaxf(mx1, fmaxf(sf[nt][2], sf[nt][3]));
        }
        mx0 = fmaxf(mx0, __shfl_xor_sync(0xffffffffu, mx0, 1));
        mx0 = fmaxf(mx0, __shfl_xor_sync(0xffffffffu, mx0, 2));
        mx1 = fmaxf(mx1, __shfl_xor_sync(0xffffffffu, mx1, 1));
        mx1 = fmaxf(mx1, __shfl_xor_sync(0xffffffffu, mx1, 2));
        float mn0 = fmaxf(m0, mx0);
        float mn1 = fmaxf(m1, mx1);
        float s0 = 0.f, s1 = 0.f;
#pragma unroll
        for (int nt = 0; nt < 8; nt++) {
            sf[nt][0] = __expf(sf[nt][0] - mn0);
            sf[nt][1] = __expf(sf[nt][1] - mn0);
            sf[nt][2] = __expf(sf[nt][2] - mn1);
            sf[nt][3] = __expf(sf[nt][3] - mn1);
            s0 += sf[nt][0] + sf[nt][1];
            s1 += sf[nt][2] + sf[nt][3];
        }
        s0 += __shfl_xor_sync(0xffffffffu, s0, 1);
        s0 += __shfl_xor_sync(0xffffffffu, s0, 2);
        s1 += __shfl_xor_sync(0xffffffffu, s1, 1);
        s1 += __shfl_xor_sync(0xffffffffu, s1, 2);
        float al0 = __expf(m0 - mn0);
        float al1 = __expf(m1 - mn1);
        l0 = l0 * al0 + s0;  m0 = mn0;
        l1 = l1 * al1 + s1;  m1 = mn1;
#pragma unroll
        for (int nt = 0; nt < 16; nt++) {
            o[nt][0] *= al0; o[nt][1] *= al0;
            o[nt][2] *= al1; o[nt][3] *= al1;
        }

        // P fragments in-register (2-term fp16 split)
        u32 ph[4][4], pl[4][4];
#pragma unroll
        for (int j = 0; j < 4; j++) {
            ph[j][0] = split2(sf[2 * j][0],     sf[2 * j][1],     pl[j][0]);
            ph[j][1] = split2(sf[2 * j][2],     sf[2 * j][3],     pl[j][1]);
            ph[j][2] = split2(sf[2 * j + 1][0], sf[2 * j + 1][1], pl[j][2]);
            ph[j][3] = split2(sf[2 * j + 1][2], sf[2 * j + 1][3], pl[j][3]);
        }

        // O += P V (2-term)
#pragma unroll
        for (int np = 0; np < 8; np++)
#pragma unroll
            for (int ks = 0; ks < 4; ks++) {
                u32 rb = (u32)(np * 16 + bRow) * (VROW * 2) + (u32)ks * 32 + bCol;
                u32 vh[4];
                ldsm_x4(vh[0], vh[1], vh[2], vh[3], base + KB_VH + rb);
                mma16816(o[np * 2 + 0], ph[ks], &vh[0]);
                mma16816(o[np * 2 + 1], ph[ks], &vh[2]);
                mma16816(o[np * 2 + 0], pl[ks], &vh[0]);
                mma16816(o[np * 2 + 1], pl[ks], &vh[2]);
            }
        __syncthreads();
    }

    // epilogue: normalize, split to fp16 hi/lo (y is A side of out_mma)
    float inv0 = 1.0f / l0;
    float inv1 = 1.0f / l1;
    __half* yhp = g_yh + (size_t)b * Tt * 2048 + (size_t)h * 128;
    __half* ylp = g_yl + (size_t)b * Tt * 2048 + (size_t)h * 128;
#pragma unroll
    for (int nt = 0; nt < 16; nt++) {
        int row = qbase + wid * 16 + g;
        int col = nt * 8 + t2;
        u32 lo0, lo1;
        u32 hi0 = split2(o[nt][0] * inv0, o[nt][1] * inv0, lo0);
        u32 hi1 = split2(o[nt][2] * inv1, o[nt][3] * inv1, lo1);
        *(u32*)(yhp + (size_t)row * 2048 + col)       = hi0;
        *(u32*)(ylp + (size_t)row * 2048 + col)       = lo0;
        *(u32*)(yhp + (size_t)(row + 8) * 2048 + col) = hi1;
        *(u32*)(ylp + (size_t)(row + 8) * 2048 + col) = lo1;
    }
}

// ================= launch =========================================================
extern "C" void kernel_launch(void* const* d_in, const int* in_sizes, int n_in,
                              void* d_out, int out_size)
{
    (void)in_sizes; (void)n_in; (void)out_size;
    const float* x  = (const float*)d_in[0];
    const float* Wq = (const float*)d_in[1];
    const float* Wk = (const float*)d_in[2];
    const float* Wv = (const float*)d_in[3];
    const float* Wo = (const float*)d_in[4];
    float* out = (float*)d_out;

    cudaFuncSetAttribute(flash_mma, cudaFuncAttributeMaxDynamicSharedMemorySize, FA_SMEM);
    cudaFuncSetAttribute(qkv_mma,   cudaFuncAttributeMaxDynamicSharedMemorySize, GEMM_SMEM);
    cudaFuncSetAttribute(out_mma,   cudaFuncAttributeMaxDynamicSharedMemorySize, GEMM_SMEM);

    const int CONV_BLKS = (BT * Cc / 4) / 256;

    cs_table_kernel<<<(Tt * 64) / 256, 256>>>();                      // 1
    conv_all<<<dim3(CONV_BLKS, 1, 5), 256>>>(x, Wq, Wk, Wv, Wo);      // 2
    qkv_mma<<<dim3(16, 16, 3), 256, GEMM_SMEM>>>();                   // 3
    prep_qk<<<(BT * Hh * 64) / 256, 256>>>();                         // 4
    prep_vt<<<dim3(16, 32), 256>>>();                                 // 5
    flash_mma<<<dim3(8, 32), 256, FA_SMEM>>>();                       // 6
    out_mma<<<dim3(16, 16), 256, GEMM_SMEM>>>(out);                   // 7
}

// round 17
// speedup vs baseline: 1.9323x; 1.3179x over previous
#include <cuda_runtime.h>
#include <cuda_fp16.h>
#include <math.h>

#define Bb 2
#define Tt 1024
#define Cc 2048
#define Hh 16
#define Dd 128
#define BT (Bb*Tt)

typedef unsigned long long u64;
typedef unsigned int u32;

// ================= portable tensor-core helpers (fp16 HMMA) =======================
__device__ __forceinline__ u32 smem_u32_of(const void* p) {
    u32 a; asm("{ .reg .u64 t; cvta.to.shared.u64 t, %1; cvt.u32.u64 %0, t; }"
               : "=r"(a) : "l"(p));
    return a;
}
__device__ __forceinline__ void ldsm_x4(u32& r0, u32& r1, u32& r2, u32& r3, u32 addr) {
    asm volatile("ldmatrix.sync.aligned.m8n8.x4.shared.b16 {%0,%1,%2,%3}, [%4];"
                 : "=r"(r0), "=r"(r1), "=r"(r2), "=r"(r3) : "r"(addr));
}
__device__ __forceinline__ void mma16816(float* c, const u32* a, const u32* b) {
    asm volatile(
        "mma.sync.aligned.m16n8k16.row.col.f32.f16.f16.f32 "
        "{%0,%1,%2,%3}, {%4,%5,%6,%7}, {%8,%9}, {%0,%1,%2,%3};"
        : "+f"(c[0]), "+f"(c[1]), "+f"(c[2]), "+f"(c[3])
        : "r"(a[0]), "r"(a[1]), "r"(a[2]), "r"(a[3]), "r"(b[0]), "r"(b[1]));
}
__device__ __forceinline__ u32 pack_h2(__half x, __half y) {
    __half2 t; t.x = x; t.y = y;
    return *(u32*)&t;
}
// split two floats into fp16-hi pair (returned) and fp16-residual pair (out)
__device__ __forceinline__ u32 split2(float x, float y, u32& lo) {
    __half hx = __float2half_rn(x);
    __half hy = __float2half_rn(y);
    lo = pack_h2(__float2half_rn(x - __half2float(hx)),
                 __float2half_rn(y - __half2float(hy)));
    return pack_h2(hx, hy);
}
__device__ __forceinline__ void cp16(u32 smem, const void* g) {
    asm volatile("cp.async.cg.shared.global [%0], [%1], 16;" :: "r"(smem), "l"(g));
}
#define CP_COMMIT() asm volatile("cp.async.commit_group;" ::: "memory")
#define CP_WAIT(n)  asm volatile("cp.async.wait_group %0;" :: "n"(n) : "memory")

// ================= scratch ========================================================
__device__ float g_q[BT * Cc];
__device__ float g_k[BT * Cc];
__device__ float g_v[BT * Cc];
__device__ float g_cos[Tt * 64];
__device__ float g_sin[Tt * 64];
__device__ __half g_xh[BT * Cc];            // x: hi only
__device__ __half g_wqh[Cc * Cc];
__device__ __half g_wkh[Cc * Cc];
__device__ __half g_wvh[Cc * Cc];
__device__ __half g_woh[Cc * Cc];
__device__ __half g_yh[BT * Cc];            // y: hi only
__device__ __half g_qhb[BT * Cc], g_qlb[BT * Cc];   // Q keeps 2-term split
__device__ __half g_khb[BT * Cc];
__device__ __half g_vth[32 * 128 * Tt];

// ================= fp32 -> fp16 conversions (one launch) ==========================
__device__ __forceinline__ void hi_store4(const float* src, __half* hi, int i)
{
    float4 v = *(const float4*)(src + i);
    *(u32*)(hi + i)     = pack_h2(__float2half_rn(v.x), __float2half_rn(v.y));
    *(u32*)(hi + i + 2) = pack_h2(__float2half_rn(v.z), __float2half_rn(v.w));
}

__global__ void __launch_bounds__(256)
conv_all(const float* x, const float* Wq, const float* Wk,
         const float* Wv, const float* Wo)
{
    int i = (blockIdx.x * blockDim.x + threadIdx.x) * 4;
    switch (blockIdx.z) {
        case 0: hi_store4(x,  g_xh,  i); break;
        case 1: hi_store4(Wq, g_wqh, i); break;
        case 2: hi_store4(Wk, g_wkh, i); break;
        case 3: hi_store4(Wv, g_wvh, i); break;
        default: hi_store4(Wo, g_woh, i); break;
    }
}

// ================= HMMA fp16 NT GEMM: C = Ah @ Bh^T ===============================
#define SROW 40
#define MATB (128 * SROW * 2)                // 10240
#define BUFB (2 * MATB)                      // Ah, Bh
#define GEMM_SMEM (2 * BUFB)                 // 40960

__device__ __forceinline__ void mma_gemm_body(
    const __half* __restrict__ Ah, const __half* __restrict__ Bh,
    float* __restrict__ Cout)
{
    extern __shared__ char sb[];
    const u32 sb32 = smem_u32_of(sb);

    const int tid = threadIdx.x;
    const int wid = tid >> 5;
    const int lane = tid & 31;
    const int bm = blockIdx.y * 128;
    const int bn = blockIdx.x * 128;
    const int m0 = (wid >> 1) * 32;
    const int n0 = (wid & 1) * 64;

    float c[2][8][4];
#pragma unroll
    for (int i = 0; i < 2; i++)
#pragma unroll
        for (int j = 0; j < 8; j++)
#pragma unroll
            for (int q = 0; q < 4; q++) c[i][j][q] = 0.f;

    const int lrow = tid >> 1;
    const int lhalf = (tid & 1) * 16;
    const size_t gA = (size_t)(bm + lrow) * 2048 + lhalf;
    const size_t gB = (size_t)(bn + lrow) * 2048 + lhalf;
    const u32 sOff = (u32)(lrow * (SROW * 2) + lhalf * 2);

    const u32 aRow = (u32)((lane & 7) + ((lane >> 3) & 1) * 8);
    const u32 aCol = (u32)(((lane >> 4) & 1) * 16);
    const u32 bRow = (u32)((lane & 7) + ((lane >> 4) & 1) * 8);
    const u32 bCol = (u32)(((lane >> 3) & 1) * 16);

    uint4 pf[4];
#pragma unroll
    for (int m = 0; m < 2; m++) {
        pf[0 + m] = *(const uint4*)(Ah + gA + m * 8);
        pf[2 + m] = *(const uint4*)(Bh + gB + m * 8);
    }

    for (int k0 = 0; k0 < 2048; k0 += 32) {
        const u32 buf = ((u32)(k0 >> 5) & 1) * BUFB;

#pragma unroll
        for (int m = 0; m < 2; m++) {
            *(uint4*)(sb + buf + 0 * MATB + sOff + m * 16) = pf[0 + m];
            *(uint4*)(sb + buf + 1 * MATB + sOff + m * 16) = pf[2 + m];
        }
        __syncthreads();

        if (k0 + 32 < 2048) {
#pragma unroll
            for (int m = 0; m < 2; m++) {
                pf[0 + m] = *(const uint4*)(Ah + gA + k0 + 32 + m * 8);
                pf[2 + m] = *(const uint4*)(Bh + gB + k0 + 32 + m * 8);
            }
        }

        const u32 baseAh = sb32 + buf;
        const u32 baseBh = baseAh + MATB;

#pragma unroll
        for (int s = 0; s < 2; s++) {
            const u32 kb = (u32)(s * 32);
            u32 ah[2][4], bh[4][4];
#pragma unroll
            for (int mi = 0; mi < 2; mi++) {
                u32 ra = (u32)(m0 + mi * 16 + aRow) * (SROW * 2) + kb + aCol;
                ldsm_x4(ah[mi][0], ah[mi][1], ah[mi][2], ah[mi][3], baseAh + ra);
            }
#pragma unroll
            for (int np = 0; np < 4; np++) {
                u32 rb = (u32)(n0 + np * 16 + bRow) * (SROW * 2) + kb + bCol;
                ldsm_x4(bh[np][0], bh[np][1], bh[np][2], bh[np][3], baseBh + rb);
            }
#pragma unroll
            for (int mi = 0; mi < 2; mi++)
#pragma unroll
                for (int np = 0; np < 4; np++) {
                    mma16816(c[mi][np * 2 + 0], ah[mi], &bh[np][0]);
                    mma16816(c[mi][np * 2 + 1], ah[mi], &bh[np][2]);
                }
        }
        __syncthreads();
    }

    const int g  = lane >> 2;
    const int tg = (lane & 3) * 2;
#pragma unroll
    for (int mi = 0; mi < 2; mi++)
#pragma unroll
        for (int nj = 0; nj < 8; nj++) {
            int row = bm + m0 + mi * 16 + g;
            int col = bn + n0 + nj * 8 + tg;
            float* cp0 = Cout + (size_t)row * 2048 + col;
            float* cp1 = Cout + (size_t)(row + 8) * 2048 + col;
            *(float2*)cp0 = make_float2(c[mi][nj][0], c[mi][nj][1]);
            *(float2*)cp1 = make_float2(c[mi][nj][2], c[mi][nj][3]);
        }
}

__global__ void __launch_bounds__(256, 1)
qkv_mma()
{
    const __half* Bh; float* out;
    if (blockIdx.z == 0)      { Bh = g_wqh; out = g_q; }
    else if (blockIdx.z == 1) { Bh = g_wkh; out = g_k; }
    else                      { Bh = g_wvh; out = g_v; }
    mma_gemm_body(g_xh, Bh, out);
}

__global__ void __launch_bounds__(256, 1)
out_mma(float* __restrict__ out)
{
    mma_gemm_body(g_yh, g_woh, out);
}

// ================= RoPE cos/sin table =============================================
__global__ void cs_table_kernel()
{
    int idx = blockIdx.x * blockDim.x + threadIdx.x;
    if (idx >= Tt * 64) return;
    int t = idx >> 6;
    int j = idx & 63;
    float invf = (float)exp(-((double)(2 * j) / 128.0) * log(10000.0));
    float thf  = (float)t * invf;
    double cd, sd;
    sincos((double)thf, &cd, &sd);
    g_cos[idx] = (float)cd;
    g_sin[idx] = (float)sd;
}

// ================= prep: rope q/k -> fp16 (Q split 2-term, K hi only) =============
__global__ void __launch_bounds__(256)
prep_qk()
{
    int idx = blockIdx.x * blockDim.x + threadIdx.x;
    int j   = idx & 63;
    int h   = (idx >> 6) & 15;
    int row = idx >> 10;
    int t   = row & (Tt - 1);

    float c = g_cos[t * 64 + j];
    float s = g_sin[t * 64 + j];
    size_t base = (size_t)row * 2048 + (size_t)h * 128 + j;

    {
        float a0 = g_q[base], a1 = g_q[base + 64];
        float r0 = a0 * c + a1 * s;
        float r1 = a1 * c - a0 * s;
        __half h0 = __float2half_rn(r0);
        __half h1 = __float2half_rn(r1);
        g_qhb[base]      = h0;
        g_qhb[base + 64] = h1;
        g_qlb[base]      = __float2half_rn(r0 - __half2float(h0));
        g_qlb[base + 64] = __float2half_rn(r1 - __half2float(h1));
    }
    {
        float a0 = g_k[base], a1 = g_k[base + 64];
        g_khb[base]      = __float2half_rn(a0 * c + a1 * s);
        g_khb[base + 64] = __float2half_rn(a1 * c - a0 * s);
    }
}

// ================= prep: transpose V -> [bh][d][t] fp16 hi ========================
__global__ void __launch_bounds__(256)
prep_vt()
{
    __shared__ float vs[128][65];
    const int tid = threadIdx.x;
    const int tt = blockIdx.x;
    const int bh = blockIdx.y;
    const int b = bh >> 4, h = bh & 15;
    const int tb = tt * 64;

    const float* vp = g_v + (size_t)b * Tt * Cc + (size_t)h * Dd;
    for (int e = tid; e < 64 * 128; e += 256) {
        int t = e >> 7, d = e & 127;
        vs[d][t] = vp[(size_t)(tb + t) * 2048 + d];
    }
    __syncthreads();

    __half* oh = g_vth + (size_t)bh * 128 * Tt + tb;
    for (int e = tid; e < 128 * 32; e += 256) {
        int d = e >> 5, tw = (e & 31) * 2;
        *(u32*)(oh + (size_t)d * Tt + tw) =
            pack_h2(__float2half_rn(vs[d][tw]), __float2half_rn(vs[d][tw + 1]));
    }
}

// ================= HMMA flash attention, fp16, cp.async (R16-verified) ============
#define QROW 136
#define VROW 72
#define KB_KH 0
#define KB_VH (64 * QROW * 2)
#define KVBUF (KB_VH + 128 * VROW * 2)
#define QH_OFF 0
#define QL_OFF (128 * QROW * 2)
#define FA_SMEM (2 * KVBUF)

__device__ __forceinline__ void fa_stage(
    char* dst, const __half* khp, const __half* vthp, int kbase, int tid)
{
    const u32 d32 = smem_u32_of(dst);
#pragma unroll
    for (int it = 0; it < 4; it++) {
        int idx = tid + it * 256;
        int r = idx >> 4, cc = idx & 15;
        size_t gk = (size_t)(kbase + r) * 2048 + cc * 8;
        cp16(d32 + KB_KH + (u32)(r * QROW + cc * 8) * 2, khp + gk);
    }
#pragma unroll
    for (int it = 0; it < 4; it++) {
        int idx = tid + it * 256;
        int d = idx >> 3, cc = idx & 7;
        size_t gv = (size_t)d * Tt + kbase + cc * 8;
        cp16(d32 + KB_VH + (u32)(d * VROW + cc * 8) * 2, vthp + gv);
    }
}

__global__ void __launch_bounds__(256, 1)
flash_mma()
{
    extern __shared__ char sb[];
    const u32 sb32 = smem_u32_of(sb);

    const int tid = threadIdx.x;
    const int wid = tid >> 5;
    const int lane = tid & 31;
    const int qt = 7 - blockIdx.x;
    const int bh = blockIdx.y;
    const int b = bh >> 4, h = bh & 15;
    const int qbase = qt * 128;
    const float scale = 0.08838834764831845f;

    const u32 aRow = (u32)((lane & 7) + ((lane >> 3) & 1) * 8);
    const u32 aCol = (u32)(((lane >> 4) & 1) * 16);
    const u32 bRow = (u32)((lane & 7) + ((lane >> 4) & 1) * 8);
    const u32 bCol = (u32)(((lane >> 3) & 1) * 16);
    const int g  = lane >> 2;
    const int t2 = (lane & 3) * 2;

    const __half* qhp = g_qhb + (size_t)b * Tt * 2048 + (size_t)h * 128;
    const __half* qlp = g_qlb + (size_t)b * Tt * 2048 + (size_t)h * 128;
    const __half* khp = g_khb + (size_t)b * Tt * 2048 + (size_t)h * 128;
    const __half* vthp = g_vth + (size_t)bh * 128 * Tt;

    for (int idx = tid; idx < 128 * 16; idx += 256) {
        int r = idx >> 4, cc = idx & 15;
        size_t gq = (size_t)(qbase + r) * 2048 + cc * 8;
        u32 so = (u32)(r * QROW + cc * 8) * 2;
        *(uint4*)(sb + QH_OFF + so) = *(const uint4*)(qhp + gq);
        *(uint4*)(sb + QL_OFF + so) = *(const uint4*)(qlp + gq);
    }
    __syncthreads();

    u32 qh[8][4], ql[8][4];
#pragma unroll
    for (int ks = 0; ks < 8; ks++) {
        u32 ra = (u32)(wid * 16 + aRow) * (QROW * 2) + (u32)ks * 32 + aCol;
        ldsm_x4(qh[ks][0], qh[ks][1], qh[ks][2], qh[ks][3], sb32 + QH_OFF + ra);
        ldsm_x4(ql[ks][0], ql[ks][1], ql[ks][2], ql[ks][3], sb32 + QL_OFF + ra);
    }
    __syncthreads();

    float o[16][4];
#pragma unroll
    for (int i = 0; i < 16; i++)
#pragma unroll
        for (int q = 0; q < 4; q++) o[i][q] = 0.f;
    float m0 = -1e30f, m1 = -1e30f, l0 = 0.f, l1 = 0.f;

    const int nkv = 2 * qt + 2;

    fa_stage(sb, khp, vthp, 0, tid);
    CP_COMMIT();

    for (int kt = 0; kt < nkv; kt++) {
        const int kbase = kt * 64;

        if (kt + 1 < nkv)
            fa_stage(sb + ((kt + 1) & 1) * KVBUF, khp, vthp, (kt + 1) * 64, tid);
        CP_COMMIT();
        CP_WAIT(1);
        __syncthreads();

        const u32 base = sb32 + (u32)(kt & 1) * KVBUF;

        float sf[8][4];
#pragma unroll
        for (int i = 0; i < 8; i++)
#pragma unroll
            for (int q = 0; q < 4; q++) sf[i][q] = 0.f;

#pragma unroll
        for (int np = 0; np < 4; np++)
#pragma unroll
            for (int ks = 0; ks < 8; ks++) {
                u32 rb = (u32)(np * 16 + bRow) * (QROW * 2) + (u32)ks * 32 + bCol;
                u32 kh[4];
                ldsm_x4(kh[0], kh[1], kh[2], kh[3], base + KB_KH + rb);
                mma16816(sf[np * 2 + 0], qh[ks], &kh[0]);
                mma16816(sf[np * 2 + 1], qh[ks], &kh[2]);
                mma16816(sf[np * 2 + 0], ql[ks], &kh[0]);
                mma16816(sf[np * 2 + 1], ql[ks], &kh[2]);
            }

#pragma unroll
        for (int nt = 0; nt < 8; nt++) {
            sf[nt][0] *= scale; sf[nt][1] *= scale;
            sf[nt][2] *= scale; sf[nt][3] *= scale;
        }
        const int row0 = qbase + wid * 16 + g;
        const int row1 = row0 + 8;
        if (kbase + 63 > qbase + wid * 16) {
#pragma unroll
            for (int nt = 0; nt < 8; nt++) {
                int col = kbase + nt * 8 + t2;
                if (col     > row0) sf[nt][0] = -1e30f;
                if (col + 1 > row0) sf[nt][1] = -1e30f;
                if (col     > row1) sf[nt][2] = -1e30f;
                if (col + 1 > row1) sf[nt][3] = -1e30f;
            }
        }

        float mx0 = -1e30f, mx1 = -1e30f;
#pragma unroll
        for (int nt = 0; nt < 8; nt++) {
            mx0 = fmaxf(mx0, fmaxf(sf[nt][0], sf[nt][1]));
            mx1 = fmaxf(mx1, fmaxf(sf[nt][2], sf[nt][3]));
        }
        mx0 = fmaxf(mx0, __shfl_xor_sync(0xffffffffu, mx0, 1));
        mx0 = fmaxf(mx0, __shfl_xor_sync(0xffffffffu, mx0, 2));
        mx1 = fmaxf(mx1, __shfl_xor_sync(0xffffffffu, mx1, 1));
        mx1 = fmaxf(mx1, __shfl_xor_sync(0xffffffffu, mx1, 2));
        float mn0 = fmaxf(m0, mx0);
        float mn1 = fmaxf(m1, mx1);
        float s0 = 0.f, s1 = 0.f;
#pragma unroll
        for (int nt = 0; nt < 8; nt++) {
            sf[nt][0] = __expf(sf[nt][0] - mn0);
            sf[nt][1] = __expf(sf[nt][1] - mn0);
            sf[nt][2] = __expf(sf[nt][2] - mn1);
            sf[nt][3] = __expf(sf[nt][3] - mn1);
            s0 += sf[nt][0] + sf[nt][1];
            s1 += sf[nt][2] + sf[nt][3];
        }
        s0 += __shfl_xor_sync(0xffffffffu, s0, 1);
        s0 += __shfl_xor_sync(0xffffffffu, s0, 2);
        s1 += __shfl_xor_sync(0xffffffffu, s1, 1);
        s1 += __shfl_xor_sync(0xffffffffu, s1, 2);
        float al0 = __expf(m0 - mn0);
        float al1 = __expf(m1 - mn1);
        l0 = l0 * al0 + s0;  m0 = mn0;
        l1 = l1 * al1 + s1;  m1 = mn1;
#pragma unroll
        for (int nt = 0; nt < 16; nt++) {
            o[nt][0] *= al0; o[nt][1] *= al0;
            o[nt][2] *= al1; o[nt][3] *= al1;
        }

        u32 ph[4][4], pl[4][4];
#pragma unroll
        for (int j = 0; j < 4; j++) {
            ph[j][0] = split2(sf[2 * j][0],     sf[2 * j][1],     pl[j][0]);
            ph[j][1] = split2(sf[2 * j][2],     sf[2 * j][3],     pl[j][1]);
            ph[j][2] = split2(sf[2 * j + 1][0], sf[2 * j + 1][1], pl[j][2]);
            ph[j][3] = split2(sf[2 * j + 1][2], sf[2 * j + 1][3], pl[j][3]);
        }

#pragma unroll
        for (int np = 0; np < 8; np++)
#pragma unroll
            for (int ks = 0; ks < 4; ks++) {
                u32 rb = (u32)(np * 16 + bRow) * (VROW * 2) + (u32)ks * 32 + bCol;
                u32 vh[4];
                ldsm_x4(vh[0], vh[1], vh[2], vh[3], base + KB_VH + rb);
                mma16816(o[np * 2 + 0], ph[ks], &vh[0]);
                mma16816(o[np * 2 + 1], ph[ks], &vh[2]);
                mma16816(o[np * 2 + 0], pl[ks], &vh[0]);
                mma16816(o[np * 2 + 1], pl[ks], &vh[2]);
            }
        __syncthreads();
    }

    // epilogue: normalize, write y hi-only fp16
    float inv0 = 1.0f / l0;
    float inv1 = 1.0f / l1;
    __half* yhp = g_yh + (size_t)b * Tt * 2048 + (size_t)h * 128;
#pragma unroll
    for (int nt = 0; nt < 16; nt++) {
        int row = qbase + wid * 16 + g;
        int col = nt * 8 + t2;
        *(u32*)(yhp + (size_t)row * 2048 + col) =
            pack_h2(__float2half_rn(o[nt][0] * inv0), __float2half_rn(o[nt][1] * inv0));
        *(u32*)(yhp + (size_t)(row + 8) * 2048 + col) =
            pack_h2(__float2half_rn(o[nt][2] * inv1), __float2half_rn(o[nt][3] * inv1));
    }
}

// ================= launch =========================================================
extern "C" void kernel_launch(void* const* d_in, const int* in_sizes, int n_in,
                              void* d_out, int out_size)
{
    (void)in_sizes; (void)n_in; (void)out_size;
    const float* x  = (const float*)d_in[0];
    const float* Wq = (const float*)d_in[1];
    const float* Wk = (const float*)d_in[2];
    const float* Wv = (const float*)d_in[3];
    const float* Wo = (const float*)d_in[4];
    float* out = (float*)d_out;

    cudaFuncSetAttribute(flash_mma, cudaFuncAttributeMaxDynamicSharedMemorySize, FA_SMEM);
    cudaFuncSetAttribute(qkv_mma,   cudaFuncAttributeMaxDynamicSharedMemorySize, GEMM_SMEM);
    cudaFuncSetAttribute(out_mma,   cudaFuncAttributeMaxDynamicSharedMemorySize, GEMM_SMEM);

    const int CONV_BLKS = (BT * Cc / 4) / 256;

    cs_table_kernel<<<(Tt * 64) / 256, 256>>>();                      // 1
    conv_all<<<dim3(CONV_BLKS, 1, 5), 256>>>(x, Wq, Wk, Wv, Wo);      // 2
    qkv_mma<<<dim3(16, 16, 3), 256, GEMM_SMEM>>>();                   // 3
    prep_qk<<<(BT * Hh * 64) / 256, 256>>>();                         // 4
    prep_vt<<<dim3(16, 32), 256>>>();                                 // 5
    flash_mma<<<dim3(8, 32), 256, FA_SMEM>>>();                       // 6
    out_mma<<<dim3(16, 16), 256, GEMM_SMEM>>>(out);                   // 7
}